// round 6
// baseline (speedup 1.0000x reference)
#include <cuda_runtime.h>
#include <cuda_bf16.h>
#include <cstdint>

// ---------------- problem constants ----------------
#define HH 512
#define TT 50003
#define NB 32
#define SL 256
#define EPSF 1e-10f
#define ENT_COEF 0.1f

#define OUT_A  ((size_t)HH)
#define OUT_B  ((size_t)HH + (size_t)HH*HH)
#define OUT_LOSS ((size_t)HH + (size_t)HH*HH + (size_t)HH*TT)

// ---------------- scratch (device globals; no allocation allowed) ----------------
__device__ float g_W[(size_t)NB*SL*HH];   // emission probs gathered per (b,s): 16 MB
__device__ float g_ll[NB];
__device__ float g_rowent[HH];
__device__ float g_colpart[8][HH];

// ---------------- reductions ----------------
__device__ __forceinline__ float warp_sum(float v){
  #pragma unroll
  for (int o=16;o;o>>=1) v += __shfl_down_sync(0xffffffffu, v, o);
  return v;
}
__device__ __forceinline__ float warp_max(float v){
  #pragma unroll
  for (int o=16;o;o>>=1) v = fmaxf(v, __shfl_down_sync(0xffffffffu, v, o));
  return v;
}
template<int NT>
__device__ __forceinline__ float block_sum(float v, float* sbuf){
  int w = threadIdx.x>>5, l = threadIdx.x&31;
  v = warp_sum(v);
  if (l==0) sbuf[w] = v;
  __syncthreads();
  if (w==0){
    float x = (l < NT/32) ? sbuf[l] : 0.f;
    x = warp_sum(x);
    if (l==0) sbuf[0] = x;
  }
  __syncthreads();
  float r = sbuf[0];
  __syncthreads();
  return r;
}
template<int NT>
__device__ __forceinline__ float block_max(float v, float* sbuf){
  int w = threadIdx.x>>5, l = threadIdx.x&31;
  v = warp_max(v);
  if (l==0) sbuf[w] = v;
  __syncthreads();
  if (w==0){
    float x = (l < NT/32) ? sbuf[l] : -3.4e38f;
    x = warp_max(x);
    if (l==0) sbuf[0] = x;
  }
  __syncthreads();
  float r = sbuf[0];
  __syncthreads();
  return r;
}

// ---------------- k_pi: softmax of init_logits -> out[0:512] ----------------
__global__ void k_pi(const float* __restrict__ il, float* __restrict__ out){
  __shared__ float sbuf[32];
  float x = il[threadIdx.x];
  float m = block_max<HH>(x, sbuf);
  float e = expf(x - m);
  float s = block_sum<HH>(e, sbuf);
  out[threadIdx.x] = e / s;
}

// ---------------- k_A: row softmax of transition_logits + per-row entropy ----------------
__global__ void k_A(const float* __restrict__ tl, float* __restrict__ out){
  __shared__ float sbuf[32];
  int i = blockIdx.x;
  float x = tl[(size_t)i*HH + threadIdx.x];
  float m = block_max<HH>(x, sbuf);
  float e = expf(x - m);
  float s = block_sum<HH>(e, sbuf);
  float p = e / s;
  out[OUT_A + (size_t)i*HH + threadIdx.x] = p;
  float ent = -p * logf(p + EPSF);
  float es = block_sum<HH>(ent, sbuf);
  if (threadIdx.x == 0) g_rowent[i] = es;
}

// ---------------- k_colpart: deterministic partial column sums of text_A ----------------
__global__ void k_colpart(const float* __restrict__ out){
  int k = blockIdx.x;            // 8 stripes of 64 rows
  int j = threadIdx.x;           // 512 columns
  const float* A = out + OUT_A + (size_t)k*64*HH;
  float s = 0.f;
  #pragma unroll 8
  for (int i = 0; i < 64; i++) s += A[(size_t)i*HH + j];
  g_colpart[k][j] = s;
}

// ---------------- k_B: row softmax of emission_logits [512 x 50003] ----------------
// Single HBM read per row: cache the whole row (200012 B) in dynamic SMEM.
#define KB_SMEM ((TT + 4) * 4)
__global__ void __launch_bounds__(1024) k_B(const float* __restrict__ el, float* __restrict__ out){
  extern __shared__ float srow[];
  __shared__ float sbuf[32];
  int r = blockIdx.x;
  const float* row = el + (size_t)r*TT;
  float* orow = out + OUT_B + (size_t)r*TT;

  float m = -3.4e38f;
  for (int idx = threadIdx.x; idx < TT; idx += 1024){
    float x = row[idx];
    srow[idx] = x;
    m = fmaxf(m, x);
  }
  __syncthreads();
  m = block_max<1024>(m, sbuf);
  float s = 0.f;
  for (int idx = threadIdx.x; idx < TT; idx += 1024){
    float e = __expf(srow[idx] - m);
    srow[idx] = e;
    s += e;
  }
  __syncthreads();
  s = block_sum<1024>(s, sbuf);
  float inv = 1.0f / s;
  for (int idx = threadIdx.x; idx < TT; idx += 1024)
    orow[idx] = srow[idx] * inv;
}

// ---------------- k_gather: W[b*S+s][h] = text_B[h][tok] + EPS ----------------
__global__ void k_gather(const int* __restrict__ text, const float* __restrict__ out){
  int bs = blockIdx.x;                    // b*SL + s
  int tok = text[bs];
  float p = out[OUT_B + (size_t)threadIdx.x*TT + (size_t)tok] + EPSF;
  g_W[(size_t)bs*HH + threadIdx.x] = p;
}

// ---------------- forward recursion: cluster of 4 CTAs per batch ----------------
#define FTH 512
#define NG  32          // i-groups (FTH / 16)
#define JSL 128         // j columns per CTA slice
#define CLS 4

#define SM_AS      0
#define SM_ALPHA   (HH*JSL*2)                 // 131072
#define SM_SCRATCH (SM_ALPHA + 2*HH*4)        // 135168
#define SM_CSUM    (SM_SCRATCH + NG*JSL*4)    // 151552  (double-buffered: 8 floats)
#define SM_RED     (SM_CSUM + 32)             // 151584
#define SM_MBAR    (SM_RED + 16)              // 151600  (2 mbarriers, ping-pong)
#define SM_TOTAL   (SM_MBAR + 16)             // 151616

__device__ __forceinline__ uint32_t s2u(const void* p){
  return (uint32_t)__cvta_generic_to_shared(p);
}
__device__ __forceinline__ void stc_f32(uint32_t a, uint32_t peer, float v){
  uint32_t r;
  asm volatile("mapa.shared::cluster.u32 %0, %1, %2;" : "=r"(r) : "r"(a), "r"(peer));
  asm volatile("st.shared::cluster.f32 [%0], %1;" :: "r"(r), "f"(v) : "memory");
}
// release-arrive at cluster scope on peer `rank`'s copy of a local mbarrier
__device__ __forceinline__ void mbar_arrive_peer(uint32_t local_mbar, uint32_t rank){
  uint32_t r;
  asm volatile("mapa.shared::cluster.u32 %0, %1, %2;" : "=r"(r) : "r"(local_mbar), "r"(rank));
  asm volatile("mbarrier.arrive.release.cluster.shared::cluster.b64 _, [%0];" :: "r"(r) : "memory");
}
// acquire-wait (cluster scope) on local mbarrier for given phase parity
__device__ __forceinline__ void mbar_wait(uint32_t mbar, uint32_t parity){
  uint32_t done;
  asm volatile("{\n\t.reg .pred p;\n\t"
    "mbarrier.try_wait.parity.acquire.cluster.shared::cta.b64 p, [%1], %2;\n\t"
    "selp.b32 %0, 1, 0, p;\n\t}"
    : "=r"(done) : "r"(mbar), "r"(parity) : "memory");
  while (!done){
    asm volatile("{\n\t.reg .pred p;\n\t"
      "mbarrier.try_wait.parity.acquire.cluster.shared::cta.b64 p, [%1], %2, 0x989680;\n\t"
      "selp.b32 %0, 1, 0, p;\n\t}"
      : "=r"(done) : "r"(mbar), "r"(parity) : "memory");
  }
}
__device__ __forceinline__ float2 bfpair(uint32_t u){
  float2 r;
  r.x = __uint_as_float(u << 16);          // bf16 lo -> fp32 (exact)
  r.y = __uint_as_float(u & 0xffff0000u);  // bf16 hi -> fp32 (exact)
  return r;
}

__global__ void __launch_bounds__(FTH, 1) k_fwd(const float* __restrict__ out){
  extern __shared__ char smem[];
  __nv_bfloat16* As = (__nv_bfloat16*)(smem + SM_AS);   // [512][128] bf16, i-major
  float* alpha   = (float*)(smem + SM_ALPHA);           // [2][512] ping-pong
  float* scratch = (float*)(smem + SM_SCRATCH);         // [NG][128]
  float* csum    = (float*)(smem + SM_CSUM);            // [2][4]
  float* red4    = (float*)(smem + SM_RED);             // [4]
  const uint32_t mbar0 = s2u(smem + SM_MBAR);           // ping-pong pair, 8 B apart

  const int tid   = threadIdx.x;
  const int rank  = blockIdx.x & 3;
  const int b     = blockIdx.x >> 2;
  const int jbase = rank * JSL;
  const float* __restrict__ A  = out + OUT_A;
  const float* __restrict__ Wb = g_W + (size_t)b*SL*HH;

  // Peer ranks (excluding self) for remote broadcasts.
  const uint32_t pr0 = (rank + 1) & 3, pr1 = (rank + 2) & 3, pr2 = (rank + 3) & 3;

  // Init ping-pong mbarriers (4 arrivals each: one per cluster CTA).
  if (tid == 0){
    asm volatile("mbarrier.init.shared.b64 [%0], %1;" :: "r"(mbar0),     "r"(CLS) : "memory");
    asm volatile("mbarrier.init.shared.b64 [%0], %1;" :: "r"(mbar0 + 8), "r"(CLS) : "memory");
  }

  // Load this CTA's A column-slice into SMEM as bf16 (coalesced over j).
  for (int idx = tid; idx < HH*JSL; idx += FTH){
    int i = idx >> 7, jl = idx & 127;
    As[idx] = __float2bfloat16(A[(size_t)i*HH + jbase + jl]);
  }
  __syncthreads();
  // All CTAs' mbarriers initialized before any remote arrive targets them.
  asm volatile("barrier.cluster.arrive.aligned;" ::: "memory");
  asm volatile("barrier.cluster.wait.aligned;"   ::: "memory");

  double ll = 0.0;
  int cur = 0;
  float inv = 1.0f;                 // deferred normalizer: folded into w each step
  int phase[2] = {0, 0};
  const int c16 = tid & 15;
  const int g   = tid >> 4;

  for (int t = 0; t < SL; t++){
    float w = 0.f, v = 0.f;
    if (tid < JSL) w = Wb[(size_t)t*HH + jbase + tid] * inv;  // emission * prev 1/c
    const int nxt = (t == 0) ? 0 : (cur ^ 1);

    if (t == 0){
      if (tid < JSL) v = (out[jbase + tid] + EPSF) * w;  // pi * W0
    } else {
      const float* acur = alpha + cur*HH;
      float acc[8];
      #pragma unroll
      for (int k = 0; k < 8; k++) acc[k] = 0.f;
      #pragma unroll 4
      for (int it = 0; it < HH/NG; it++){                // 16 iters, i = g + 32*it
        int i = g + it*NG;
        float a = acur[i];
        uint4 pk = *((const uint4*)(As + i*JSL + c16*8));
        float2 p0 = bfpair(pk.x), p1 = bfpair(pk.y), p2 = bfpair(pk.z), p3 = bfpair(pk.w);
        acc[0] += a*p0.x; acc[1] += a*p0.y;
        acc[2] += a*p1.x; acc[3] += a*p1.y;
        acc[4] += a*p2.x; acc[5] += a*p2.y;
        acc[6] += a*p3.x; acc[7] += a*p3.y;
      }
      float4* s0 = (float4*)(scratch + g*JSL + c16*8);
      s0[0] = make_float4(acc[0],acc[1],acc[2],acc[3]);
      s0[1] = make_float4(acc[4],acc[5],acc[6],acc[7]);
      __syncthreads();
      if (tid < JSL){
        float r0=0.f, r1=0.f, r2=0.f, r3=0.f;
        #pragma unroll
        for (int g2 = 0; g2 < NG; g2 += 4){
          r0 += scratch[(g2+0)*JSL + tid];
          r1 += scratch[(g2+1)*JSL + tid];
          r2 += scratch[(g2+2)*JSL + tid];
          r3 += scratch[(g2+3)*JSL + tid];
        }
        v = ((r0+r1)+(r2+r3)) * w;
      }
    }

    // Broadcast slice to the 3 peers via DSMEM; own copy via plain STS.
    float* anext = alpha + nxt*HH;
    float* cb    = csum  + nxt*4;
    if (tid < JSL){
      anext[jbase + tid] = v;                       // local copy (cheap STS)
      uint32_t aadr = s2u(anext + jbase + tid);
      stc_f32(aadr, pr0, v); stc_f32(aadr, pr1, v); stc_f32(aadr, pr2, v);
      float sv = warp_sum(v);
      if ((tid & 31) == 0) red4[tid >> 5] = sv;
    }
    __syncthreads();   // orders ALL threads' DSMEM stores before tid0's release-arrives
    const int bsel = t & 1;
    const uint32_t mb = mbar0 + (uint32_t)(bsel * 8);
    if (tid == 0){
      float ps = red4[0]+red4[1]+red4[2]+red4[3];
      cb[rank] = ps;                                // local copy
      uint32_t cadr = s2u(cb + rank);
      stc_f32(cadr, pr0, ps); stc_f32(cadr, pr1, ps); stc_f32(cadr, pr2, ps);
      mbar_arrive_peer(mb, 0); mbar_arrive_peer(mb, 1);
      mbar_arrive_peer(mb, 2); mbar_arrive_peer(mb, 3);
    }
    mbar_wait(mb, (uint32_t)phase[bsel]);
    phase[bsel] ^= 1;

    float ctot = (cb[0]+cb[1]) + (cb[2]+cb[3]);
    inv = 1.0f / ctot;               // applied via w at step t+1 (linearity)
    if (tid == 0) ll += (double)logf(ctot);
    cur = nxt;
  }
  if (rank == 0 && tid == 0) g_ll[b] = (float)ll;

  // Exit fence: no CTA leaves while any peer DSMEM traffic could be in flight.
  asm volatile("barrier.cluster.arrive.aligned;" ::: "memory");
  asm volatile("barrier.cluster.wait.aligned;"   ::: "memory");
}

// ---------------- final scalar loss ----------------
__global__ void k_loss(const float* __restrict__ thr, float* __restrict__ out){
  __shared__ float sbuf[32];
  int tid = threadIdx.x;   // 512
  float cs = 0.f;
  #pragma unroll
  for (int k = 0; k < 8; k++) cs += g_colpart[k][tid];
  float thv = thr ? *thr : 0.5f;
  float pen = fmaxf(thv - cs, 0.f);
  float pen_s = block_sum<HH>(pen, sbuf);
  float ent_s = block_sum<HH>(g_rowent[tid], sbuf);
  float llv = (tid < NB) ? g_ll[tid] : 0.f;
  float ll_s = block_sum<HH>(llv, sbuf);
  if (tid == 0)
    out[OUT_LOSS] = -(ll_s / (float)NB) + (ent_s / (float)HH) * ENT_COEF + pen_s * 1.0f;
}

// ---------------- launch ----------------
extern "C" void kernel_launch(void* const* d_in, const int* in_sizes, int n_in,
                              void* d_out, int out_size){
  // Bind inputs by element count (all distinct) — robust to metadata ordering.
  const int*   text = nullptr;
  const float* il = nullptr, *tl = nullptr, *el = nullptr, *thr = nullptr;
  for (int k = 0; k < n_in; k++){
    switch (in_sizes[k]){
      case NB*SL:        text = (const int*)  d_in[k]; break;  // 8192
      case HH:           il   = (const float*)d_in[k]; break;  // 512
      case HH*HH:        tl   = (const float*)d_in[k]; break;  // 262144
      case 1:            thr  = (const float*)d_in[k]; break;
      default:
        if ((size_t)in_sizes[k] == (size_t)HH*TT) el = (const float*)d_in[k];
        break;
    }
  }
  float* out = (float*)d_out;

  cudaFuncSetAttribute(k_B,   cudaFuncAttributeMaxDynamicSharedMemorySize, KB_SMEM);
  cudaFuncSetAttribute(k_fwd, cudaFuncAttributeMaxDynamicSharedMemorySize, SM_TOTAL);

  k_pi<<<1, HH>>>(il, out);
  k_A<<<HH, HH>>>(tl, out);
  k_colpart<<<8, HH>>>(out);
  k_B<<<HH, 1024, KB_SMEM>>>(el, out);
  k_gather<<<NB*SL, HH>>>(text, out);

  cudaLaunchConfig_t cfg = {};
  cfg.gridDim  = dim3(NB*CLS, 1, 1);
  cfg.blockDim = dim3(FTH, 1, 1);
  cfg.dynamicSmemBytes = SM_TOTAL;
  cfg.stream = 0;
  cudaLaunchAttribute at[1];
  at[0].id = cudaLaunchAttributeClusterDimension;
  at[0].val.clusterDim.x = CLS;
  at[0].val.clusterDim.y = 1;
  at[0].val.clusterDim.z = 1;
  cfg.attrs = at;
  cfg.numAttrs = 1;
  cudaLaunchKernelEx(&cfg, k_fwd, (const float*)out);

  k_loss<<<1, HH>>>(thr, out);
}

// round 10
// speedup vs baseline: 1.3924x; 1.3924x over previous
#include <cuda_runtime.h>
#include <cuda_bf16.h>
#include <cstdint>

// ---------------- problem constants ----------------
#define HH 512
#define TT 50003
#define NB 32
#define SL 256
#define EPSF 1e-10f
#define ENT_COEF 0.1f

#define OUT_A  ((size_t)HH)
#define OUT_B  ((size_t)HH + (size_t)HH*HH)
#define OUT_LOSS ((size_t)HH + (size_t)HH*HH + (size_t)HH*TT)

// ---------------- scratch (device globals; no allocation allowed) ----------------
__device__ float g_W[(size_t)NB*SL*HH];   // emission probs gathered per (b,s): 16 MB
__device__ float g_ll[NB];
__device__ float g_rowent[HH];
__device__ float g_colpart[8][HH];
__device__ float g_bmax[HH];              // per-row softmax max of emission_logits
__device__ float g_binv[HH];              // per-row 1/sum

// ---------------- reductions ----------------
__device__ __forceinline__ float warp_sum(float v){
  #pragma unroll
  for (int o=16;o;o>>=1) v += __shfl_down_sync(0xffffffffu, v, o);
  return v;
}
__device__ __forceinline__ float warp_max(float v){
  #pragma unroll
  for (int o=16;o;o>>=1) v = fmaxf(v, __shfl_down_sync(0xffffffffu, v, o));
  return v;
}
template<int NT>
__device__ __forceinline__ float block_sum(float v, float* sbuf){
  int w = threadIdx.x>>5, l = threadIdx.x&31;
  v = warp_sum(v);
  if (l==0) sbuf[w] = v;
  __syncthreads();
  if (w==0){
    float x = (l < NT/32) ? sbuf[l] : 0.f;
    x = warp_sum(x);
    if (l==0) sbuf[0] = x;
  }
  __syncthreads();
  float r = sbuf[0];
  __syncthreads();
  return r;
}
template<int NT>
__device__ __forceinline__ float block_max(float v, float* sbuf){
  int w = threadIdx.x>>5, l = threadIdx.x&31;
  v = warp_max(v);
  if (l==0) sbuf[w] = v;
  __syncthreads();
  if (w==0){
    float x = (l < NT/32) ? sbuf[l] : -3.4e38f;
    x = warp_max(x);
    if (l==0) sbuf[0] = x;
  }
  __syncthreads();
  float r = sbuf[0];
  __syncthreads();
  return r;
}

// ---------------- k_pi ----------------
__global__ void k_pi(const float* __restrict__ il, float* __restrict__ out){
  __shared__ float sbuf[32];
  float x = il[threadIdx.x];
  float m = block_max<HH>(x, sbuf);
  float e = expf(x - m);
  float s = block_sum<HH>(e, sbuf);
  out[threadIdx.x] = e / s;
}

// ---------------- k_A: row softmax + per-row entropy ----------------
__global__ void k_A(const float* __restrict__ tl, float* __restrict__ out){
  __shared__ float sbuf[32];
  int i = blockIdx.x;
  float x = tl[(size_t)i*HH + threadIdx.x];
  float m = block_max<HH>(x, sbuf);
  float e = expf(x - m);
  float s = block_sum<HH>(e, sbuf);
  float p = e / s;
  out[OUT_A + (size_t)i*HH + threadIdx.x] = p;
  float ent = -p * logf(p + EPSF);
  float es = block_sum<HH>(ent, sbuf);
  if (threadIdx.x == 0) g_rowent[i] = es;
}

// ---------------- k_colpart ----------------
__global__ void k_colpart(const float* __restrict__ out){
  int k = blockIdx.x;
  int j = threadIdx.x;
  const float* A = out + OUT_A + (size_t)k*64*HH;
  float s = 0.f;
  #pragma unroll 8
  for (int i = 0; i < 64; i++) s += A[(size_t)i*HH + j];
  g_colpart[k][j] = s;
}

// ---------------- k_Bstats: per-row (max, 1/sum) of emission_logits ----------------
// Single DRAM read via SMEM cache, float4-vectorized for MLP. No output write.
#define KB_SMEM ((TT + 4) * 4)
__global__ void __launch_bounds__(1024) k_Bstats(const float* __restrict__ el){
  extern __shared__ float srow[];
  __shared__ float sbuf[32];
  const int r   = blockIdx.x;
  const int tid = threadIdx.x;
  const float* row = el + (size_t)r*TT;

  const int p = (int)(((16u - ((uint32_t)(uintptr_t)row & 15u)) & 15u) >> 2);
  float m = -3.4e38f;
  if (tid < p){ float x = row[tid]; srow[tid] = x; m = fmaxf(m, x); }
  const int nvec = (TT - p) >> 2;
  const float4* rv = (const float4*)(row + p);
  #pragma unroll 4
  for (int idx = tid; idx < nvec; idx += 1024){
    float4 q = rv[idx];
    int base = p + idx*4;
    srow[base]   = q.x; srow[base+1] = q.y;
    srow[base+2] = q.z; srow[base+3] = q.w;
    m = fmaxf(fmaxf(fmaxf(m, q.x), fmaxf(q.y, q.z)), q.w);
  }
  const int tail = p + nvec*4;
  for (int idx = tail + tid; idx < TT; idx += 1024){
    float x = row[idx]; srow[idx] = x; m = fmaxf(m, x);
  }
  __syncthreads();
  m = block_max<1024>(m, sbuf);
  float s = 0.f;
  #pragma unroll 4
  for (int idx = tid; idx < TT; idx += 1024)
    s += __expf(srow[idx] - m);
  s = block_sum<1024>(s, sbuf);
  if (tid == 0){ g_bmax[r] = m; g_binv[r] = 1.0f / s; }
}

// ---------------- k_Bwrite: materialize text_B (off critical path, side stream) ----
__global__ void __launch_bounds__(1024) k_Bwrite(const float* __restrict__ el,
                                                 float* __restrict__ out){
  const int r   = blockIdx.x;
  const int tid = threadIdx.x;
  const float* row = el + (size_t)r*TT;
  float* orow = out + OUT_B + (size_t)r*TT;
  const float m = g_bmax[r], inv = g_binv[r];

  // el row and out row share the same mod-16B phase (OUT_B % 4 == 0).
  const int p = (int)(((16u - ((uint32_t)(uintptr_t)row & 15u)) & 15u) >> 2);
  if (tid < p) orow[tid] = __expf(row[tid] - m) * inv;
  const int nvec = (TT - p) >> 2;
  const float4* rv = (const float4*)(row + p);
  float4* wv = (float4*)(orow + p);
  #pragma unroll 4
  for (int idx = tid; idx < nvec; idx += 1024){
    float4 q = rv[idx];
    wv[idx] = make_float4(__expf(q.x - m)*inv, __expf(q.y - m)*inv,
                          __expf(q.z - m)*inv, __expf(q.w - m)*inv);
  }
  const int tail = p + nvec*4;
  for (int idx = tail + tid; idx < TT; idx += 1024)
    orow[idx] = __expf(row[idx] - m) * inv;
}

// ---------------- k_gather: W from el + stats (bit-identical to text_B + EPS) ----
__global__ void k_gather(const int* __restrict__ text, const float* __restrict__ el){
  int bs = blockIdx.x;
  int tok = text[bs];
  int h = threadIdx.x;
  float x = el[(size_t)h*TT + (size_t)tok];
  g_W[(size_t)bs*HH + h] = __expf(x - g_bmax[h]) * g_binv[h] + EPSF;
}

// ---------------- forward recursion ----------------
#define FTH 512
#define NG  32
#define JSL 128
#define CLS 4
#define RM  6                 // i-iterations with A in registers (fp32)
#define REGROWS (32*RM)       // 192
#define SMROWS (HH - REGROWS) // 320 rows of A in SMEM (bf16)

#define SM_AS      0
#define SM_ALPHA   (SMROWS*JSL*2)             // 81920
#define SM_SCRATCH (SM_ALPHA + 2*HH*4)        // 86016
#define SM_CSUM    (SM_SCRATCH + NG*JSL*4)    // 102400
#define SM_RED     (SM_CSUM + 32)             // 102432
#define SM_MBAR    (SM_RED + 16)              // 102448
#define SM_TOTAL   (SM_MBAR + 16)             // 102464

typedef unsigned long long ull;

__device__ __forceinline__ uint32_t s2u(const void* p){
  return (uint32_t)__cvta_generic_to_shared(p);
}
__device__ __forceinline__ void stc_f32(uint32_t a, uint32_t peer, float v){
  uint32_t r;
  asm volatile("mapa.shared::cluster.u32 %0, %1, %2;" : "=r"(r) : "r"(a), "r"(peer));
  asm volatile("st.shared::cluster.f32 [%0], %1;" :: "r"(r), "f"(v) : "memory");
}
__device__ __forceinline__ void mbar_arrive_peer(uint32_t local_mbar, uint32_t rank){
  uint32_t r;
  asm volatile("mapa.shared::cluster.u32 %0, %1, %2;" : "=r"(r) : "r"(local_mbar), "r"(rank));
  asm volatile("mbarrier.arrive.release.cluster.shared::cluster.b64 _, [%0];" :: "r"(r) : "memory");
}
__device__ __forceinline__ void mbar_wait(uint32_t mbar, uint32_t parity){
  uint32_t done;
  asm volatile("{\n\t.reg .pred p;\n\t"
    "mbarrier.try_wait.parity.acquire.cluster.shared::cta.b64 p, [%1], %2;\n\t"
    "selp.b32 %0, 1, 0, p;\n\t}"
    : "=r"(done) : "r"(mbar), "r"(parity) : "memory");
  while (!done){
    asm volatile("{\n\t.reg .pred p;\n\t"
      "mbarrier.try_wait.parity.acquire.cluster.shared::cta.b64 p, [%1], %2, 0x989680;\n\t"
      "selp.b32 %0, 1, 0, p;\n\t}"
      : "=r"(done) : "r"(mbar), "r"(parity) : "memory");
  }
}
__device__ __forceinline__ ull pk2(float lo, float hi){
  ull r;
  asm("mov.b64 %0, {%1, %2};" : "=l"(r) : "f"(lo), "f"(hi));
  return r;
}
__device__ __forceinline__ ull bf2(uint32_t u){
  uint32_t lo = u << 16, hi = u & 0xffff0000u;
  ull r;
  asm("mov.b64 %0, {%1, %2};" : "=l"(r) : "r"(lo), "r"(hi));
  return r;
}
__device__ __forceinline__ ull fma2(ull a, ull b, ull c){
  ull d;
  asm("fma.rn.f32x2 %0, %1, %2, %3;" : "=l"(d) : "l"(a), "l"(b), "l"(c));
  return d;
}

__global__ void __launch_bounds__(FTH, 1) k_fwd(const float* __restrict__ out){
  extern __shared__ char smem[];
  __nv_bfloat16* As = (__nv_bfloat16*)(smem + SM_AS);   // [320][128] bf16, rows 192..511
  float* alpha   = (float*)(smem + SM_ALPHA);           // [2][512] ping-pong
  float* scratch = (float*)(smem + SM_SCRATCH);         // [NG][128]
  float* csum    = (float*)(smem + SM_CSUM);            // [2][4]
  float* red4    = (float*)(smem + SM_RED);             // [4]
  const uint32_t mbar0 = s2u(smem + SM_MBAR);

  const int tid   = threadIdx.x;
  const int rank  = blockIdx.x & 3;
  const int b     = blockIdx.x >> 2;
  const int jbase = rank * JSL;
  const float* __restrict__ A  = out + OUT_A;
  const float* __restrict__ Wb = g_W + (size_t)b*SL*HH;

  const uint32_t pr0 = (rank + 1) & 3, pr1 = (rank + 2) & 3, pr2 = (rank + 3) & 3;
  const int c16 = tid & 15;
  const int g   = tid >> 4;

  if (tid == 0){
    asm volatile("mbarrier.init.shared.b64 [%0], %1;" :: "r"(mbar0),     "r"(CLS) : "memory");
    asm volatile("mbarrier.init.shared.b64 [%0], %1;" :: "r"(mbar0 + 8), "r"(CLS) : "memory");
  }

  // SMEM half of A: rows [192,512) as bf16 (coalesced over j).
  for (int idx = tid; idx < SMROWS*JSL; idx += FTH){
    int ir = idx >> 7, jl = idx & 127;
    As[idx] = __float2bfloat16(A[(size_t)(REGROWS + ir)*HH + jbase + jl]);
  }
  // Register half of A: rows i = g + 32m, m<RM, this thread's 8 j's, exact fp32.
  ull Ar[RM][4];
  #pragma unroll
  for (int m = 0; m < RM; m++){
    const float* rp = A + (size_t)(g + 32*m)*HH + jbase + c16*8;
    float4 q0 = *(const float4*)(rp);
    float4 q1 = *(const float4*)(rp + 4);
    Ar[m][0] = pk2(q0.x, q0.y); Ar[m][1] = pk2(q0.z, q0.w);
    Ar[m][2] = pk2(q1.x, q1.y); Ar[m][3] = pk2(q1.z, q1.w);
  }
  __syncthreads();
  asm volatile("barrier.cluster.arrive.aligned;" ::: "memory");
  asm volatile("barrier.cluster.wait.aligned;"   ::: "memory");

  double ll = 0.0;
  int cur = 0;
  float inv = 1.0f;
  int phase[2] = {0, 0};

  for (int t = 0; t < SL; t++){
    float w = 0.f, v = 0.f;
    if (tid < JSL) w = Wb[(size_t)t*HH + jbase + tid] * inv;
    const int nxt = (t == 0) ? 0 : (cur ^ 1);

    if (t == 0){
      if (tid < JSL) v = (out[jbase + tid] + EPSF) * w;
    } else {
      const float* acur = alpha + cur*HH;
      ull acc[4] = {0ull, 0ull, 0ull, 0ull};
      #pragma unroll
      for (int m = 0; m < RM; m++){
        float a = acur[g + 32*m];
        ull ap = pk2(a, a);
        acc[0] = fma2(Ar[m][0], ap, acc[0]);
        acc[1] = fma2(Ar[m][1], ap, acc[1]);
        acc[2] = fma2(Ar[m][2], ap, acc[2]);
        acc[3] = fma2(Ar[m][3], ap, acc[3]);
      }
      #pragma unroll
      for (int m = RM; m < 16; m++){
        int i = g + 32*m;
        float a = acur[i];
        ull ap = pk2(a, a);
        uint4 pk = *((const uint4*)(As + (i - REGROWS)*JSL + c16*8));
        acc[0] = fma2(bf2(pk.x), ap, acc[0]);
        acc[1] = fma2(bf2(pk.y), ap, acc[1]);
        acc[2] = fma2(bf2(pk.z), ap, acc[2]);
        acc[3] = fma2(bf2(pk.w), ap, acc[3]);
      }
      ull* s64 = (ull*)(scratch + g*JSL + c16*8);
      s64[0] = acc[0]; s64[1] = acc[1]; s64[2] = acc[2]; s64[3] = acc[3];
      __syncthreads();
      if (tid < JSL){
        float r0=0.f, r1=0.f, r2=0.f, r3=0.f;
        #pragma unroll
        for (int g2 = 0; g2 < NG; g2 += 4){
          r0 += scratch[(g2+0)*JSL + tid];
          r1 += scratch[(g2+1)*JSL + tid];
          r2 += scratch[(g2+2)*JSL + tid];
          r3 += scratch[(g2+3)*JSL + tid];
        }
        v = ((r0+r1)+(r2+r3)) * w;
      }
    }

    float* anext = alpha + nxt*HH;
    float* cb    = csum  + nxt*4;
    if (tid < JSL){
      anext[jbase + tid] = v;
      uint32_t aadr = s2u(anext + jbase + tid);
      stc_f32(aadr, pr0, v); stc_f32(aadr, pr1, v); stc_f32(aadr, pr2, v);
      float sv = warp_sum(v);
      if ((tid & 31) == 0) red4[tid >> 5] = sv;
    }
    __syncthreads();   // orders all DSMEM stores before the release-arrives below
    const int bsel = t & 1;
    const uint32_t mb = mbar0 + (uint32_t)(bsel * 8);
    if (tid < 4){
      float ps = red4[0]+red4[1]+red4[2]+red4[3];
      uint32_t cadr = s2u(cb + rank);
      stc_f32(cadr, (uint32_t)tid, ps);
      mbar_arrive_peer(mb, (uint32_t)tid);
    }
    mbar_wait(mb, (uint32_t)phase[bsel]);
    phase[bsel] ^= 1;

    float ctot = (cb[0]+cb[1]) + (cb[2]+cb[3]);
    inv = 1.0f / ctot;
    if (tid == 0) ll += (double)logf(ctot);
    cur = nxt;
  }
  if (rank == 0 && tid == 0) g_ll[b] = (float)ll;

  asm volatile("barrier.cluster.arrive.aligned;" ::: "memory");
  asm volatile("barrier.cluster.wait.aligned;"   ::: "memory");
}

// ---------------- final scalar loss ----------------
__global__ void k_loss(const float* __restrict__ thr, float* __restrict__ out){
  __shared__ float sbuf[32];
  int tid = threadIdx.x;
  float cs = 0.f;
  #pragma unroll
  for (int k = 0; k < 8; k++) cs += g_colpart[k][tid];
  float thv = thr ? *thr : 0.5f;
  float pen = fmaxf(thv - cs, 0.f);
  float pen_s = block_sum<HH>(pen, sbuf);
  float ent_s = block_sum<HH>(g_rowent[tid], sbuf);
  float llv = (tid < NB) ? g_ll[tid] : 0.f;
  float ll_s = block_sum<HH>(llv, sbuf);
  if (tid == 0)
    out[OUT_LOSS] = -(ll_s / (float)NB) + (ent_s / (float)HH) * ENT_COEF + pen_s * 1.0f;
}

// ---------------- launch ----------------
extern "C" void kernel_launch(void* const* d_in, const int* in_sizes, int n_in,
                              void* d_out, int out_size){
  const int*   text = nullptr;
  const float* il = nullptr, *tl = nullptr, *el = nullptr, *thr = nullptr;
  for (int k = 0; k < n_in; k++){
    switch (in_sizes[k]){
      case NB*SL:        text = (const int*)  d_in[k]; break;
      case HH:           il   = (const float*)d_in[k]; break;
      case HH*HH:        tl   = (const float*)d_in[k]; break;
      case 1:            thr  = (const float*)d_in[k]; break;
      default:
        if ((size_t)in_sizes[k] == (size_t)HH*TT) el = (const float*)d_in[k];
        break;
    }
  }
  float* out = (float*)d_out;

  // Lazily created side-stream + fork/join events (first call runs outside
  // graph capture). Work per call is identical; these are handles, not state
  // that changes the captured graph between calls.
  static cudaStream_t s1 = nullptr;
  static cudaEvent_t evF = nullptr, evJ = nullptr;
  if (!s1){
    cudaStreamCreateWithFlags(&s1, cudaStreamNonBlocking);
    cudaEventCreateWithFlags(&evF, cudaEventDisableTiming);
    cudaEventCreateWithFlags(&evJ, cudaEventDisableTiming);
  }

  cudaFuncSetAttribute(k_Bstats, cudaFuncAttributeMaxDynamicSharedMemorySize, KB_SMEM);
  cudaFuncSetAttribute(k_fwd,    cudaFuncAttributeMaxDynamicSharedMemorySize, SM_TOTAL);

  k_pi<<<1, HH>>>(il, out);
  k_A<<<HH, HH>>>(tl, out);
  k_colpart<<<8, HH>>>(out);
  k_Bstats<<<HH, 1024, KB_SMEM>>>(el);
  k_gather<<<NB*SL, HH>>>(text, el);

  // Fork: text_B materialization runs on s1, overlapped with k_fwd.
  cudaEventRecord(evF, 0);
  cudaStreamWaitEvent(s1, evF, 0);
  k_Bwrite<<<HH, 1024, 0, s1>>>(el, out);
  cudaEventRecord(evJ, s1);

  cudaLaunchConfig_t cfg = {};
  cfg.gridDim  = dim3(NB*CLS, 1, 1);
  cfg.blockDim = dim3(FTH, 1, 1);
  cfg.dynamicSmemBytes = SM_TOTAL;
  cfg.stream = 0;
  cudaLaunchAttribute at[1];
  at[0].id = cudaLaunchAttributeClusterDimension;
  at[0].val.clusterDim.x = CLS;
  at[0].val.clusterDim.y = 1;
  at[0].val.clusterDim.z = 1;
  cfg.attrs = at;
  cfg.numAttrs = 1;
  cudaLaunchKernelEx(&cfg, k_fwd, (const float*)out);

  // Join before the final kernel so the captured graph has no dangling branch.
  cudaStreamWaitEvent(0, evJ, 0);
  k_loss<<<1, HH>>>(thr, out);
}